// round 10
// baseline (speedup 1.0000x reference)
#include <cuda_runtime.h>
#include <cuda_bf16.h>
#include <cstdint>
#include <cstddef>

// ---------------------------------------------------------------------------
// Problem constants
// ---------------------------------------------------------------------------
#define B_  256
#define T_  100
#define I_  1024
#define H_  2048
#define O_  10
#define M1  (B_ * T_)   // 25600

// Tile: 64x64 CTA, 16 warps (4m x 4n), warp tile 16x16; BK=64
#define BM 64
#define BN 64
#define BKS 64
#define STRS 72                        // 144B rows; conflict-free ldmatrix
#define SLOTS (BM * STRS)              // 4608 elems per array per stage
#define NTHREADS 512

// step kernel: 4 stages
#define NSTG_S 4
#define ABYTESS (NSTG_S * SLOTS * 2)   // 36864 B per operand array
#define SMEM_S  (4 * ABYTESS)          // 147456 B
#define NBLK_STEP 128
#define NROWG 4
#define GRP_CTAS 32

// xin kernel: 3 stages
#define NSTG_X 3
#define ABYTESX (NSTG_X * SLOTS * 2)   // 27648 B per operand array
#define SMEM_X  (4 * ABYTESX)          // 110592 B

// ---------------------------------------------------------------------------
// Device scratch
// ---------------------------------------------------------------------------
__device__ float g_xin [(size_t)T_ * B_ * H_];           // [t][b][h]
__device__ __nv_bfloat16 g_hh_hi[(size_t)T_ * B_ * H_];
__device__ __nv_bfloat16 g_hh_lo[(size_t)T_ * B_ * H_];
__device__ __nv_bfloat16 g_xhi[(size_t)M1 * I_];
__device__ __nv_bfloat16 g_xlo[(size_t)M1 * I_];
__device__ __nv_bfloat16 g_WinT_hi[(size_t)H_ * I_];     // [h][i]
__device__ __nv_bfloat16 g_WinT_lo[(size_t)H_ * I_];
__device__ __nv_bfloat16 g_WT_hi[(size_t)H_ * H_];       // [n][k]
__device__ __nv_bfloat16 g_WT_lo[(size_t)H_ * H_];
__device__ __nv_bfloat16 g_hA_hi[(size_t)B_ * H_], g_hA_lo[(size_t)B_ * H_];
__device__ unsigned g_bar_count4[NROWG] = {0, 0, 0, 0};
__device__ unsigned g_bar_sense4[NROWG] = {0, 0, 0, 0};

// ---------------------------------------------------------------------------
// Helpers
// ---------------------------------------------------------------------------
__device__ __forceinline__ uint32_t s2u(const void* p) {
    uint32_t a;
    asm("{ .reg .u64 t; cvta.to.shared.u64 t, %1; cvt.u32.u64 %0, t; }" : "=r"(a) : "l"(p));
    return a;
}
__device__ __forceinline__ void cp16(uint32_t s, const void* g) {
    asm volatile("cp.async.cg.shared.global [%0], [%1], 16;" :: "r"(s), "l"(g));
}
#define CP_COMMIT()  asm volatile("cp.async.commit_group;")
#define CP_WAIT(N)   asm volatile("cp.async.wait_group %0;" :: "n"(N))

__device__ __forceinline__ void mma_bf16(float* d, const uint32_t* a, uint32_t b0, uint32_t b1) {
    asm volatile(
        "mma.sync.aligned.m16n8k16.row.col.f32.bf16.bf16.f32 "
        "{%0,%1,%2,%3}, {%4,%5,%6,%7}, {%8,%9}, {%0,%1,%2,%3};"
        : "+f"(d[0]), "+f"(d[1]), "+f"(d[2]), "+f"(d[3])
        : "r"(a[0]), "r"(a[1]), "r"(a[2]), "r"(a[3]), "r"(b0), "r"(b1));
}
__device__ __forceinline__ void ldsm4(uint32_t* r, uint32_t addr) {
    asm volatile("ldmatrix.sync.aligned.m8n8.x4.shared.b16 {%0,%1,%2,%3}, [%4];"
        : "=r"(r[0]), "=r"(r[1]), "=r"(r[2]), "=r"(r[3]) : "r"(addr));
}
__device__ __forceinline__ void split2(float v, __nv_bfloat16& h, __nv_bfloat16& l) {
    h = __float2bfloat16(v);
    l = __float2bfloat16(v - __bfloat162float(h));
}

// bf16x3 compute, warp tile 16x16 (NJ=2): per k16 half, 4 ldsm4 + 6 MMA.
__device__ __forceinline__ void compute_stage_lm16(
    uint32_t sAh, uint32_t sAl, uint32_t sBh, uint32_t sBl,
    uint32_t a_off, uint32_t b_off, float (*d)[4])
{
    #pragma unroll
    for (int kh = 0; kh < 4; kh++) {       // BK=64 -> 4 k16 halves
        const uint32_t ko = kh * 32;
        uint32_t ah[4], al[4], bh[4], bl[4];
        ldsm4(ah, sAh + a_off + ko);
        ldsm4(al, sAl + a_off + ko);
        ldsm4(bh, sBh + b_off + ko);
        ldsm4(bl, sBl + b_off + ko);
        mma_bf16(d[0], ah, bh[0], bh[1]);
        mma_bf16(d[0], ah, bl[0], bl[1]);
        mma_bf16(d[0], al, bh[0], bh[1]);
        mma_bf16(d[1], ah, bh[2], bh[3]);
        mma_bf16(d[1], ah, bl[2], bl[3]);
        mma_bf16(d[1], al, bh[2], bh[3]);
    }
}
__device__ __forceinline__ uint32_t a_lane_off(int mrow, int lane) {
    return (uint32_t)(((mrow + (lane & 15)) * STRS + ((lane >> 4) & 1) * 8) * 2);
}
// 16-wide B group: lanes 0-7 n..n+8 k+0 | 8-15 k+8 | 16-23 n+8..n+16 k+0 | 24-31 k+8
__device__ __forceinline__ uint32_t b_lane_off(int ncol, int lane) {
    return (uint32_t)(((ncol + ((lane >> 4) & 1) * 8 + (lane & 7)) * STRS
                       + ((lane >> 3) & 1) * 8) * 2);
}

// ---------------------------------------------------------------------------
// Prologue kernels
// ---------------------------------------------------------------------------
__global__ void decomp_kernel(const float* __restrict__ src,
                              __nv_bfloat16* __restrict__ hi,
                              __nv_bfloat16* __restrict__ lo, size_t n4) {
    for (size_t i = (size_t)blockIdx.x * blockDim.x + threadIdx.x; i < n4;
         i += (size_t)gridDim.x * blockDim.x) {
        float4 v = ((const float4*)src)[i];
        __nv_bfloat16 h0, l0, h1, l1, h2, l2, h3, l3;
        split2(v.x, h0, l0); split2(v.y, h1, l1);
        split2(v.z, h2, l2); split2(v.w, h3, l3);
        ((__nv_bfloat162*)hi)[i * 2 + 0] = __halves2bfloat162(h0, h1);
        ((__nv_bfloat162*)hi)[i * 2 + 1] = __halves2bfloat162(h2, h3);
        ((__nv_bfloat162*)lo)[i * 2 + 0] = __halves2bfloat162(l0, l1);
        ((__nv_bfloat162*)lo)[i * 2 + 1] = __halves2bfloat162(l2, l3);
    }
}

__global__ void transpose_decomp_kernel(const float* __restrict__ src, int R, int C,
                                        __nv_bfloat16* __restrict__ dhi,
                                        __nv_bfloat16* __restrict__ dlo) {
    __shared__ float tile[32][33];
    const int bx = blockIdx.x * 32;
    const int by = blockIdx.y * 32;
    const int tx = threadIdx.x, ty = threadIdx.y;
    #pragma unroll
    for (int j = 0; j < 32; j += 8)
        tile[ty + j][tx] = src[(size_t)(by + ty + j) * C + bx + tx];
    __syncthreads();
    #pragma unroll
    for (int j = 0; j < 32; j += 8) {
        float v = tile[tx][ty + j];
        size_t o = (size_t)(bx + ty + j) * R + by + tx;
        __nv_bfloat16 h, l; split2(v, h, l);
        dhi[o] = h; dlo[o] = l;
    }
}

// ---------------------------------------------------------------------------
// xin GEMM: g_xin[t][b][:] = x @ Win.  512 thr, BK=64, 3-stage.
// ---------------------------------------------------------------------------
__global__ void __launch_bounds__(NTHREADS) xin_gemm_kernel() {
    extern __shared__ __nv_bfloat16 sm[];
    const uint32_t sbase = s2u(sm);
    const uint32_t pAh = sbase;
    const uint32_t pAl = sbase + 1 * ABYTESX;
    const uint32_t pBh = sbase + 2 * ABYTESX;
    const uint32_t pBl = sbase + 3 * ABYTESX;

    const int tid = threadIdx.x;
    const int wid = tid >> 5, lane = tid & 31;
    const int mrow = (wid & 3) * 16;
    const int ncol = (wid >> 2) * 16;
    const int rowBase = blockIdx.y * BM;
    const int colBase = blockIdx.x * BN;
    const int lr = tid >> 3;               // 0..63
    const int lc = (tid & 7) * 8;          // 0..56
    constexpr int NK = I_ / BKS;   // 16

    const uint32_t a_off = a_lane_off(mrow, lane);
    const uint32_t b_off = b_lane_off(ncol, lane);

    auto issue = [&](int slot, int kc) {
        const int k0 = kc * BKS;
        const size_t ga = (size_t)(rowBase + lr) * I_ + k0 + lc;
        const size_t gb = (size_t)(colBase + lr) * I_ + k0 + lc;
        const uint32_t so = (uint32_t)(slot * SLOTS + lr * STRS + lc) * 2;
        cp16(pAh + so, g_xhi + ga);
        cp16(pAl + so, g_xlo + ga);
        cp16(pBh + so, g_WinT_hi + gb);
        cp16(pBl + so, g_WinT_lo + gb);
        CP_COMMIT();
    };

    issue(0, 0); issue(1, 1);
    float d[2][4] = {};

    int slot = 0;
    #pragma unroll 1
    for (int kc = 0; kc < NK; kc++) {
        CP_WAIT(1);
        __syncthreads();
        if (kc + 2 < NK) {
            int s2 = slot + 2; if (s2 >= NSTG_X) s2 -= NSTG_X;
            issue(s2, kc + 2);
        }
        const uint32_t so = (uint32_t)(slot * SLOTS) * 2;
        compute_stage_lm16(pAh + so, pAl + so, pBh + so, pBl + so, a_off, b_off, d);
        if (++slot == NSTG_X) slot = 0;
    }
    CP_WAIT(0);

    const int g = lane >> 2, tg = lane & 3;
    const int r0 = rowBase + mrow + g;
    const int r1 = r0 + 8;
    const int bb0 = r0 / T_, tt0 = r0 - bb0 * T_;
    const int bb1 = r1 / T_, tt1 = r1 - bb1 * T_;
    #pragma unroll
    for (int j = 0; j < 2; j++) {
        const int col = colBase + ncol + j * 8 + 2 * tg;
        *(float2*)&g_xin[((size_t)tt0 * B_ + bb0) * H_ + col] = make_float2(d[j][0], d[j][1]);
        *(float2*)&g_xin[((size_t)tt1 * B_ + bb1) * H_ + col] = make_float2(d[j][2], d[j][3]);
    }
}

// ---------------------------------------------------------------------------
// Per-rowgroup split grid barrier (32 arrivals each)
// ---------------------------------------------------------------------------
__device__ __forceinline__ void bar_arrive(int grp, unsigned target) {
    __threadfence();
    __syncthreads();
    if (threadIdx.x == 0) {
        unsigned a = atomicAdd(&g_bar_count4[grp], 1);
        if (a == GRP_CTAS - 1) {
            atomicExch(&g_bar_count4[grp], 0);
            __threadfence();
            atomicExch(&g_bar_sense4[grp], target);
        }
    }
}
__device__ __forceinline__ void bar_wait(int grp, unsigned target) {
    if (threadIdx.x == 0) {
        while (atomicAdd(&g_bar_sense4[grp], 0) < target) { __nanosleep(64); }
    }
    __syncthreads();
}

// ---------------------------------------------------------------------------
// Persistent recurrence: 512 thr, BK=64, 4-stage, W prefetch, rowgroup bars.
// ---------------------------------------------------------------------------
__global__ void __launch_bounds__(NTHREADS) step_persistent_kernel() {
    extern __shared__ __nv_bfloat16 sm[];
    const uint32_t sbase = s2u(sm);
    const uint32_t pAh = sbase;
    const uint32_t pAl = sbase + 1 * ABYTESS;
    const uint32_t pBh = sbase + 2 * ABYTESS;
    const uint32_t pBl = sbase + 3 * ABYTESS;

    const int tid = threadIdx.x;
    const int wid = tid >> 5, lane = tid & 31;
    const int mrow = (wid & 3) * 16;
    const int ncol = (wid >> 2) * 16;
    const int bid = blockIdx.x;
    const int grp = bid >> 5;
    const int rowBase = grp * BM;
    const int colBase = (bid & 31) * BN;
    const int lr = tid >> 3;               // 0..63
    const int lc = (tid & 7) * 8;          // 0..56
    constexpr int NK = H_ / BKS;   // 32

    const uint32_t a_off = a_lane_off(mrow, lane);
    const uint32_t b_off = b_lane_off(ncol, lane);

    __shared__ unsigned s_base;
    if (tid == 0) s_base = atomicAdd(&g_bar_sense4[grp], 0u);
    __syncthreads();
    const unsigned base = s_base;

    auto issueW = [&](int slot, int kc) {
        const int k0 = kc * BKS;
        const size_t gb = (size_t)(colBase + lr) * H_ + k0 + lc;
        const uint32_t so = (uint32_t)(slot * SLOTS + lr * STRS + lc) * 2;
        cp16(pBh + so, g_WT_hi + gb);
        cp16(pBl + so, g_WT_lo + gb);
        CP_COMMIT();
    };

    issueW(0, 0); issueW(1, 1); issueW(2, 2);

    #pragma unroll 1
    for (int t = 0; t < T_; t++) {
        const __nv_bfloat16* ah = (t == 0) ? g_hA_hi : (g_hh_hi + (size_t)(t - 1) * B_ * H_);
        const __nv_bfloat16* al = (t == 0) ? g_hA_lo : (g_hh_lo + (size_t)(t - 1) * B_ * H_);
        __nv_bfloat16* whi = g_hh_hi + (size_t)t * B_ * H_;
        __nv_bfloat16* wlo = g_hh_lo + (size_t)t * B_ * H_;

        auto issueA = [&](int slot, int kc) {
            const int k0 = kc * BKS;
            const size_t ga = (size_t)(rowBase + lr) * H_ + k0 + lc;
            const uint32_t so = (uint32_t)(slot * SLOTS + lr * STRS + lc) * 2;
            cp16(pAh + so, ah + ga);
            cp16(pAl + so, al + ga);
            CP_COMMIT();
        };
        auto issueWA = [&](int slot, int kc) {
            const int k0 = kc * BKS;
            const size_t ga = (size_t)(rowBase + lr) * H_ + k0 + lc;
            const size_t gb = (size_t)(colBase + lr) * H_ + k0 + lc;
            const uint32_t so = (uint32_t)(slot * SLOTS + lr * STRS + lc) * 2;
            cp16(pAh + so, ah + ga);
            cp16(pAl + so, al + ga);
            cp16(pBh + so, g_WT_hi + gb);
            cp16(pBl + so, g_WT_lo + gb);
            CP_COMMIT();
        };

        if (t > 0) bar_wait(grp, base + (unsigned)t);
        issueA(0, 0); issueA(1, 1); issueA(2, 2);

        float d[2][4] = {};

        #pragma unroll 1
        for (int kc = 0; kc < NK; kc++) {
            CP_WAIT(2);
            __syncthreads();
            if (kc + 3 < NK) issueWA((kc + 3) & 3, kc + 3);
            else             issueW((kc + 3 - NK) & 3, kc + 3 - NK);
            const uint32_t so = (uint32_t)((kc & 3) * SLOTS) * 2;
            compute_stage_lm16(pAh + so, pAl + so, pBh + so, pBl + so, a_off, b_off, d);
        }

        // Epilogue: h = tanh(xin + acc) -> bf16 hi/lo history
        const int g = lane >> 2, tg = lane & 3;
        const int r0 = rowBase + mrow + g;
        const int r1 = r0 + 8;
        #pragma unroll
        for (int j = 0; j < 2; j++) {
            const int col = colBase + ncol + j * 8 + 2 * tg;
            const size_t o0 = ((size_t)t * B_ + r0) * H_ + col;
            const size_t o1 = ((size_t)t * B_ + r1) * H_ + col;
            float2 x0 = *(const float2*)&g_xin[o0];
            float2 x1 = *(const float2*)&g_xin[o1];
            float h00 = tanhf(x0.x + d[j][0]);
            float h01 = tanhf(x0.y + d[j][1]);
            float h10 = tanhf(x1.x + d[j][2]);
            float h11 = tanhf(x1.y + d[j][3]);
            __nv_bfloat16 e0, f0, e1, f1, e2, f2, e3, f3;
            split2(h00, e0, f0); split2(h01, e1, f1);
            split2(h10, e2, f2); split2(h11, e3, f3);
            const size_t w0 = (size_t)r0 * H_ + col;
            const size_t w1 = (size_t)r1 * H_ + col;
            *(__nv_bfloat162*)&whi[w0] = __halves2bfloat162(e0, e1);
            *(__nv_bfloat162*)&wlo[w0] = __halves2bfloat162(f0, f1);
            *(__nv_bfloat162*)&whi[w1] = __halves2bfloat162(e2, e3);
            *(__nv_bfloat162*)&wlo[w1] = __halves2bfloat162(f2, f3);
        }

        if (t < T_ - 1) bar_arrive(grp, base + (unsigned)t + 1u);
    }
    CP_WAIT(0);
}

// ---------------------------------------------------------------------------
// Output head: h reconstructed from bf16 hi+lo history
// ---------------------------------------------------------------------------
__global__ void __launch_bounds__(256) out_kernel(
    const float* __restrict__ lin_w,
    const float* __restrict__ lin_b,
    float* __restrict__ out)
{
    const int bt = blockIdx.x;
    const int t = bt / B_;
    const int b = bt % B_;
    const int tid = threadIdx.x;

    const __nv_bfloat16* hhi = g_hh_hi + ((size_t)t * B_ + b) * H_;
    const __nv_bfloat16* hlo = g_hh_lo + ((size_t)t * B_ + b) * H_;

    float hreg[H_ / 256];
    #pragma unroll
    for (int i = 0; i < H_ / 256; i++)
        hreg[i] = __bfloat162float(hhi[i * 256 + tid]) + __bfloat162float(hlo[i * 256 + tid]);

    float acc[O_];
    #pragma unroll
    for (int o = 0; o < O_; o++) {
        float s = 0.f;
        #pragma unroll
        for (int i = 0; i < H_ / 256; i++)
            s += hreg[i] * lin_w[(size_t)o * H_ + i * 256 + tid];
        acc[o] = s;
    }

    #pragma unroll
    for (int off = 16; off > 0; off >>= 1)
        #pragma unroll
        for (int o = 0; o < O_; o++)
            acc[o] += __shfl_xor_sync(0xFFFFFFFFu, acc[o], off);

    __shared__ float wsum[8][O_];
    const int lane = tid & 31;
    const int w = tid >> 5;
    if (lane == 0)
        #pragma unroll
        for (int o = 0; o < O_; o++)
            wsum[w][o] = acc[o];
    __syncthreads();

    if (tid < O_) {
        float s = lin_b[tid];
        #pragma unroll
        for (int ww = 0; ww < 8; ww++)
            s += wsum[ww][tid];
        out[((size_t)b * T_ + t) * O_ + tid] = s;
    }
}

// ---------------------------------------------------------------------------
extern "C" void kernel_launch(void* const* d_in, const int* in_sizes, int n_in,
                              void* d_out, int out_size)
{
    const float* x     = (const float*)d_in[0];
    const float* h0    = (const float*)d_in[1];
    const float* Win   = (const float*)d_in[2];
    const float* W     = (const float*)d_in[3];
    const float* lin_w = (const float*)d_in[4];
    const float* lin_b = (const float*)d_in[5];
    float* out = (float*)d_out;

    __nv_bfloat16 *xhi, *xlo, *winT_hi, *winT_lo, *wT_hi, *wT_lo, *hA_hi, *hA_lo;
    cudaGetSymbolAddress((void**)&xhi, g_xhi);
    cudaGetSymbolAddress((void**)&xlo, g_xlo);
    cudaGetSymbolAddress((void**)&winT_hi, g_WinT_hi);
    cudaGetSymbolAddress((void**)&winT_lo, g_WinT_lo);
    cudaGetSymbolAddress((void**)&wT_hi, g_WT_hi);
    cudaGetSymbolAddress((void**)&wT_lo, g_WT_lo);
    cudaGetSymbolAddress((void**)&hA_hi, g_hA_hi);
    cudaGetSymbolAddress((void**)&hA_lo, g_hA_lo);

    static bool attr_done = false;
    if (!attr_done) {
        cudaFuncSetAttribute(xin_gemm_kernel,
                             cudaFuncAttributeMaxDynamicSharedMemorySize, SMEM_X);
        cudaFuncSetAttribute(step_persistent_kernel,
                             cudaFuncAttributeMaxDynamicSharedMemorySize, SMEM_S);
        attr_done = true;
    }

    // Prologue
    decomp_kernel<<<4096, 256>>>(x, xhi, xlo, (size_t)M1 * I_ / 4);
    decomp_kernel<<<512, 256>>>(h0, hA_hi, hA_lo, (size_t)B_ * H_ / 4);
    transpose_decomp_kernel<<<dim3(H_ / 32, I_ / 32), dim3(32, 8)>>>(Win, I_, H_, winT_hi, winT_lo);
    transpose_decomp_kernel<<<dim3(H_ / 32, H_ / 32), dim3(32, 8)>>>(W, H_, H_, wT_hi, wT_lo);

    // Input projection
    xin_gemm_kernel<<<dim3(H_ / BN, M1 / BM), NTHREADS, SMEM_X>>>();

    // Full recurrence
    step_persistent_kernel<<<NBLK_STEP, NTHREADS, SMEM_S>>>();

    // Output head
    out_kernel<<<T_ * B_, 256>>>(lin_w, lin_b, out);
}

// round 11
// speedup vs baseline: 1.0682x; 1.0682x over previous
#include <cuda_runtime.h>
#include <cuda_bf16.h>
#include <cstdint>
#include <cstddef>

// ---------------------------------------------------------------------------
// Problem constants
// ---------------------------------------------------------------------------
#define B_  256
#define T_  100
#define I_  1024
#define H_  2048
#define O_  10
#define M1  (B_ * T_)   // 25600

// Tile: 64x64 CTA, 8 warps; BK=64
#define BM 64
#define BN 64
#define BKS 64
#define STRS 72                        // 144B rows; conflict-free ldmatrix
#define SLOTS (BM * STRS)              // 4608 elems per array per stage

// step kernel: 4 stages
#define NSTG_S 4
#define ABYTESS (NSTG_S * SLOTS * 2)   // 36864 B per operand array
#define SMEM_S  (4 * ABYTESS)          // 147456 B
#define NBLK_STEP 128
#define NROWG 4
#define GRP_CTAS 32

// xin kernel: 3 stages
#define NSTG_X 3
#define ABYTESX (NSTG_X * SLOTS * 2)   // 27648 B per operand array
#define SMEM_X  (4 * ABYTESX)          // 110592 B

// ---------------------------------------------------------------------------
// Device scratch
// ---------------------------------------------------------------------------
__device__ float g_xin [(size_t)T_ * B_ * H_];           // [t][b][h]
__device__ __nv_bfloat16 g_hh_hi[(size_t)T_ * B_ * H_];
__device__ __nv_bfloat16 g_hh_lo[(size_t)T_ * B_ * H_];
__device__ __nv_bfloat16 g_xhi[(size_t)M1 * I_];
__device__ __nv_bfloat16 g_xlo[(size_t)M1 * I_];
__device__ __nv_bfloat16 g_WinT_hi[(size_t)H_ * I_];     // [h][i]
__device__ __nv_bfloat16 g_WinT_lo[(size_t)H_ * I_];
__device__ __nv_bfloat16 g_WT_hi[(size_t)H_ * H_];       // [n][k]
__device__ __nv_bfloat16 g_WT_lo[(size_t)H_ * H_];
__device__ __nv_bfloat16 g_hA_hi[(size_t)B_ * H_], g_hA_lo[(size_t)B_ * H_];
__device__ unsigned g_bar_count4[NROWG] = {0, 0, 0, 0};
__device__ unsigned g_bar_sense4[NROWG] = {0, 0, 0, 0};

// ---------------------------------------------------------------------------
// Helpers
// ---------------------------------------------------------------------------
__device__ __forceinline__ uint32_t s2u(const void* p) {
    uint32_t a;
    asm("{ .reg .u64 t; cvta.to.shared.u64 t, %1; cvt.u32.u64 %0, t; }" : "=r"(a) : "l"(p));
    return a;
}
__device__ __forceinline__ void cp16(uint32_t s, const void* g) {
    asm volatile("cp.async.cg.shared.global [%0], [%1], 16;" :: "r"(s), "l"(g));
}
#define CP_COMMIT()  asm volatile("cp.async.commit_group;")
#define CP_WAIT(N)   asm volatile("cp.async.wait_group %0;" :: "n"(N))

__device__ __forceinline__ void mma_bf16(float* d, const uint32_t* a, uint32_t b0, uint32_t b1) {
    asm volatile(
        "mma.sync.aligned.m16n8k16.row.col.f32.bf16.bf16.f32 "
        "{%0,%1,%2,%3}, {%4,%5,%6,%7}, {%8,%9}, {%0,%1,%2,%3};"
        : "+f"(d[0]), "+f"(d[1]), "+f"(d[2]), "+f"(d[3])
        : "r"(a[0]), "r"(a[1]), "r"(a[2]), "r"(a[3]), "r"(b0), "r"(b1));
}
__device__ __forceinline__ void ldsm4(uint32_t* r, uint32_t addr) {
    asm volatile("ldmatrix.sync.aligned.m8n8.x4.shared.b16 {%0,%1,%2,%3}, [%4];"
        : "=r"(r[0]), "=r"(r[1]), "=r"(r[2]), "=r"(r[3]) : "r"(addr));
}
__device__ __forceinline__ void split2(float v, __nv_bfloat16& h, __nv_bfloat16& l) {
    h = __float2bfloat16(v);
    l = __float2bfloat16(v - __bfloat162float(h));
}

__device__ __forceinline__ uint32_t a_lane_off(int mrow, int lane) {
    return (uint32_t)(((mrow + (lane & 15)) * STRS + ((lane >> 4) & 1) * 8) * 2);
}
__device__ __forceinline__ uint32_t b_lane_off(int ncol, int jp, int lane) {
    return (uint32_t)(((ncol + jp * 16 + ((lane >> 4) & 1) * 8 + (lane & 7)) * STRS
                       + ((lane >> 3) & 1) * 8) * 2);
}

// xin compute: warp 16x32, all 4 kh (R9-proven)
__device__ __forceinline__ void compute_stage_x(
    uint32_t sAh, uint32_t sAl, uint32_t sBh, uint32_t sBl,
    uint32_t a_off, uint32_t b_off0, uint32_t b_off1, float (*d)[4])
{
    #pragma unroll
    for (int kh = 0; kh < 4; kh++) {
        const uint32_t ko = kh * 32;
        uint32_t ah[4], al[4], bh[4], bl[4];
        ldsm4(ah, sAh + a_off + ko);
        ldsm4(al, sAl + a_off + ko);
        ldsm4(bh, sBh + b_off0 + ko);
        ldsm4(bl, sBl + b_off0 + ko);
        mma_bf16(d[0], ah, bh[0], bh[1]);
        mma_bf16(d[0], ah, bl[0], bl[1]);
        mma_bf16(d[0], al, bh[0], bh[1]);
        mma_bf16(d[1], ah, bh[2], bh[3]);
        mma_bf16(d[1], ah, bl[2], bl[3]);
        mma_bf16(d[1], al, bh[2], bh[3]);
        ldsm4(bh, sBh + b_off1 + ko);
        ldsm4(bl, sBl + b_off1 + ko);
        mma_bf16(d[2], ah, bh[0], bh[1]);
        mma_bf16(d[2], ah, bl[0], bl[1]);
        mma_bf16(d[2], al, bh[0], bh[1]);
        mma_bf16(d[3], ah, bh[2], bh[3]);
        mma_bf16(d[3], ah, bl[2], bl[3]);
        mma_bf16(d[3], al, bh[2], bh[3]);
    }
}

// step compute: warp 32x32 over HALF the chunk K (kh = khb, khb+1).
// 8 ldsm4 / 24 MMA per kh -> 170 B/MMA smem traffic.
__device__ __forceinline__ void compute_stage_k32(
    uint32_t sAh, uint32_t sAl, uint32_t sBh, uint32_t sBl,
    uint32_t a_off0, uint32_t a_off1, uint32_t b_off0, uint32_t b_off1,
    int khb, float (*d)[4][4])   // d[mi][nj][4]
{
    #pragma unroll
    for (int i = 0; i < 2; i++) {
        const uint32_t ko = (khb + i) * 32;
        uint32_t ah0[4], ah1[4], al0[4], al1[4], bh0[4], bh1[4], bl0[4], bl1[4];
        ldsm4(ah0, sAh + a_off0 + ko);
        ldsm4(ah1, sAh + a_off1 + ko);
        ldsm4(al0, sAl + a_off0 + ko);
        ldsm4(al1, sAl + a_off1 + ko);
        ldsm4(bh0, sBh + b_off0 + ko);
        ldsm4(bh1, sBh + b_off1 + ko);
        ldsm4(bl0, sBl + b_off0 + ko);
        ldsm4(bl1, sBl + b_off1 + ko);
        // mi=0
        mma_bf16(d[0][0], ah0, bh0[0], bh0[1]);
        mma_bf16(d[0][1], ah0, bh0[2], bh0[3]);
        mma_bf16(d[0][2], ah0, bh1[0], bh1[1]);
        mma_bf16(d[0][3], ah0, bh1[2], bh1[3]);
        mma_bf16(d[0][0], ah0, bl0[0], bl0[1]);
        mma_bf16(d[0][1], ah0, bl0[2], bl0[3]);
        mma_bf16(d[0][2], ah0, bl1[0], bl1[1]);
        mma_bf16(d[0][3], ah0, bl1[2], bl1[3]);
        mma_bf16(d[0][0], al0, bh0[0], bh0[1]);
        mma_bf16(d[0][1], al0, bh0[2], bh0[3]);
        mma_bf16(d[0][2], al0, bh1[0], bh1[1]);
        mma_bf16(d[0][3], al0, bh1[2], bh1[3]);
        // mi=1
        mma_bf16(d[1][0], ah1, bh0[0], bh0[1]);
        mma_bf16(d[1][1], ah1, bh0[2], bh0[3]);
        mma_bf16(d[1][2], ah1, bh1[0], bh1[1]);
        mma_bf16(d[1][3], ah1, bh1[2], bh1[3]);
        mma_bf16(d[1][0], ah1, bl0[0], bl0[1]);
        mma_bf16(d[1][1], ah1, bl0[2], bl0[3]);
        mma_bf16(d[1][2], ah1, bl1[0], bl1[1]);
        mma_bf16(d[1][3], ah1, bl1[2], bl1[3]);
        mma_bf16(d[1][0], al1, bh0[0], bh0[1]);
        mma_bf16(d[1][1], al1, bh0[2], bh0[3]);
        mma_bf16(d[1][2], al1, bh1[0], bh1[1]);
        mma_bf16(d[1][3], al1, bh1[2], bh1[3]);
    }
}

// ---------------------------------------------------------------------------
// Prologue kernels
// ---------------------------------------------------------------------------
__global__ void decomp_kernel(const float* __restrict__ src,
                              __nv_bfloat16* __restrict__ hi,
                              __nv_bfloat16* __restrict__ lo, size_t n4) {
    for (size_t i = (size_t)blockIdx.x * blockDim.x + threadIdx.x; i < n4;
         i += (size_t)gridDim.x * blockDim.x) {
        float4 v = ((const float4*)src)[i];
        __nv_bfloat16 h0, l0, h1, l1, h2, l2, h3, l3;
        split2(v.x, h0, l0); split2(v.y, h1, l1);
        split2(v.z, h2, l2); split2(v.w, h3, l3);
        ((__nv_bfloat162*)hi)[i * 2 + 0] = __halves2bfloat162(h0, h1);
        ((__nv_bfloat162*)hi)[i * 2 + 1] = __halves2bfloat162(h2, h3);
        ((__nv_bfloat162*)lo)[i * 2 + 0] = __halves2bfloat162(l0, l1);
        ((__nv_bfloat162*)lo)[i * 2 + 1] = __halves2bfloat162(l2, l3);
    }
}

__global__ void transpose_decomp_kernel(const float* __restrict__ src, int R, int C,
                                        __nv_bfloat16* __restrict__ dhi,
                                        __nv_bfloat16* __restrict__ dlo) {
    __shared__ float tile[32][33];
    const int bx = blockIdx.x * 32;
    const int by = blockIdx.y * 32;
    const int tx = threadIdx.x, ty = threadIdx.y;
    #pragma unroll
    for (int j = 0; j < 32; j += 8)
        tile[ty + j][tx] = src[(size_t)(by + ty + j) * C + bx + tx];
    __syncthreads();
    #pragma unroll
    for (int j = 0; j < 32; j += 8) {
        float v = tile[tx][ty + j];
        size_t o = (size_t)(bx + ty + j) * R + by + tx;
        __nv_bfloat16 h, l; split2(v, h, l);
        dhi[o] = h; dlo[o] = l;
    }
}

// ---------------------------------------------------------------------------
// xin GEMM: g_xin[t][b][:] = x @ Win.  BK=64, 3-stage, 2 CTAs/SM. (R9)
// ---------------------------------------------------------------------------
__global__ void __launch_bounds__(256, 2) xin_gemm_kernel() {
    extern __shared__ __nv_bfloat16 sm[];
    const uint32_t sbase = s2u(sm);
    const uint32_t pAh = sbase;
    const uint32_t pAl = sbase + 1 * ABYTESX;
    const uint32_t pBh = sbase + 2 * ABYTESX;
    const uint32_t pBl = sbase + 3 * ABYTESX;

    const int tid = threadIdx.x;
    const int wid = tid >> 5, lane = tid & 31;
    const int mrow = (wid & 3) * 16;
    const int ncol = (wid >> 2) * 32;
    const int rowBase = blockIdx.y * BM;
    const int colBase = blockIdx.x * BN;
    const int lr = tid >> 3;               // 0..31
    const int lc = (tid & 7) * 8;          // 0..56
    constexpr int NK = I_ / BKS;   // 16

    const uint32_t a_off  = a_lane_off(mrow, lane);
    const uint32_t b_off0 = b_lane_off(ncol, 0, lane);
    const uint32_t b_off1 = b_lane_off(ncol, 1, lane);

    auto issue = [&](int slot, int kc) {
        const int k0 = kc * BKS;
        #pragma unroll
        for (int i = 0; i < 2; i++) {
            const size_t ga = (size_t)(rowBase + lr + i * 32) * I_ + k0 + lc;
            const size_t gb = (size_t)(colBase + lr + i * 32) * I_ + k0 + lc;
            const uint32_t so = (uint32_t)(slot * SLOTS + (lr + i * 32) * STRS + lc) * 2;
            cp16(pAh + so, g_xhi + ga);
            cp16(pAl + so, g_xlo + ga);
            cp16(pBh + so, g_WinT_hi + gb);
            cp16(pBl + so, g_WinT_lo + gb);
        }
        CP_COMMIT();
    };

    issue(0, 0); issue(1, 1);
    float d[4][4] = {};

    int slot = 0;
    #pragma unroll 1
    for (int kc = 0; kc < NK; kc++) {
        CP_WAIT(1);
        __syncthreads();
        if (kc + 2 < NK) {
            int s2 = slot + 2; if (s2 >= NSTG_X) s2 -= NSTG_X;
            issue(s2, kc + 2);
        }
        const uint32_t so = (uint32_t)(slot * SLOTS) * 2;
        compute_stage_x(pAh + so, pAl + so, pBh + so, pBl + so,
                        a_off, b_off0, b_off1, d);
        if (++slot == NSTG_X) slot = 0;
    }
    CP_WAIT(0);

    const int g = lane >> 2, tg = lane & 3;
    const int r0 = rowBase + mrow + g;
    const int r1 = r0 + 8;
    const int bb0 = r0 / T_, tt0 = r0 - bb0 * T_;
    const int bb1 = r1 / T_, tt1 = r1 - bb1 * T_;
    #pragma unroll
    for (int j = 0; j < 4; j++) {
        const int col = colBase + ncol + j * 8 + 2 * tg;
        *(float2*)&g_xin[((size_t)tt0 * B_ + bb0) * H_ + col] = make_float2(d[j][0], d[j][1]);
        *(float2*)&g_xin[((size_t)tt1 * B_ + bb1) * H_ + col] = make_float2(d[j][2], d[j][3]);
    }
}

// ---------------------------------------------------------------------------
// Per-rowgroup split grid barrier (32 arrivals each)
// ---------------------------------------------------------------------------
__device__ __forceinline__ void bar_arrive(int grp, unsigned target) {
    __threadfence();
    __syncthreads();
    if (threadIdx.x == 0) {
        unsigned a = atomicAdd(&g_bar_count4[grp], 1);
        if (a == GRP_CTAS - 1) {
            atomicExch(&g_bar_count4[grp], 0);
            __threadfence();
            atomicExch(&g_bar_sense4[grp], target);
        }
    }
}
__device__ __forceinline__ void bar_wait(int grp, unsigned target) {
    if (threadIdx.x == 0) {
        while (atomicAdd(&g_bar_sense4[grp], 0) < target) { __nanosleep(64); }
    }
    __syncthreads();
}

// ---------------------------------------------------------------------------
// Persistent recurrence: 8 warps, split-K (warps 0-3: kh 0-1, warps 4-7: kh 2-3),
// warp tile 32x32, BK=64, 4 stages, cross-step W prefetch, rowgroup barriers.
// ---------------------------------------------------------------------------
__global__ void __launch_bounds__(256) step_persistent_kernel() {
    extern __shared__ __nv_bfloat16 sm[];
    const uint32_t sbase = s2u(sm);
    const uint32_t pAh = sbase;
    const uint32_t pAl = sbase + 1 * ABYTESS;
    const uint32_t pBh = sbase + 2 * ABYTESS;
    const uint32_t pBl = sbase + 3 * ABYTESS;

    const int tid = threadIdx.x;
    const int wid = tid >> 5, lane = tid & 31;
    const int mrow = (wid & 1) * 32;          // 2 m halves
    const int ncol = ((wid >> 1) & 1) * 32;   // 2 n halves
    const int khb  = (wid >> 2) * 2;          // K-slice: 0 or 2
    const int bid = blockIdx.x;
    const int grp = bid >> 5;
    const int rowBase = grp * BM;
    const int colBase = (bid & 31) * BN;
    const int lr = tid >> 3;               // 0..31
    const int lc = (tid & 7) * 8;          // 0..56
    constexpr int NK = H_ / BKS;   // 32

    const uint32_t a_off0 = a_lane_off(mrow, lane);
    const uint32_t a_off1 = a_lane_off(mrow + 16, lane);
    const uint32_t b_off0 = b_lane_off(ncol, 0, lane);
    const uint32_t b_off1 = b_lane_off(ncol, 1, lane);

    // reduction exchange regions: slot 3 of pAh / pAl (free at step end)
    const uint32_t redA = pAh + (uint32_t)(3 * SLOTS) * 2;
    const uint32_t redB = pAl + (uint32_t)(3 * SLOTS) * 2;

    __shared__ unsigned s_base;
    if (tid == 0) s_base = atomicAdd(&g_bar_sense4[grp], 0u);
    __syncthreads();
    const unsigned base = s_base;

    auto issueW = [&](int slot, int kc) {
        const int k0 = kc * BKS;
        #pragma unroll
        for (int i = 0; i < 2; i++) {
            const size_t gb = (size_t)(colBase + lr + i * 32) * H_ + k0 + lc;
            const uint32_t so = (uint32_t)(slot * SLOTS + (lr + i * 32) * STRS + lc) * 2;
            cp16(pBh + so, g_WT_hi + gb);
            cp16(pBl + so, g_WT_lo + gb);
        }
        CP_COMMIT();
    };

    issueW(0, 0); issueW(1, 1); issueW(2, 2);

    #pragma unroll 1
    for (int t = 0; t < T_; t++) {
        const __nv_bfloat16* ah = (t == 0) ? g_hA_hi : (g_hh_hi + (size_t)(t - 1) * B_ * H_);
        const __nv_bfloat16* al = (t == 0) ? g_hA_lo : (g_hh_lo + (size_t)(t - 1) * B_ * H_);
        __nv_bfloat16* whi = g_hh_hi + (size_t)t * B_ * H_;
        __nv_bfloat16* wlo = g_hh_lo + (size_t)t * B_ * H_;

        auto issueA = [&](int slot, int kc) {
            const int k0 = kc * BKS;
            #pragma unroll
            for (int i = 0; i < 2; i++) {
                const size_t ga = (size_t)(rowBase + lr + i * 32) * H_ + k0 + lc;
                const uint32_t so = (uint32_t)(slot * SLOTS + (lr + i * 32) * STRS + lc) * 2;
                cp16(pAh + so, ah + ga);
                cp16(pAl + so, al + ga);
            }
            CP_COMMIT();
        };
        auto issueWA = [&](int slot, int kc) {
            const int k0 = kc * BKS;
            #pragma unroll
            for (int i = 0; i < 2; i++) {
                const size_t ga = (size_t)(rowBase + lr + i * 32) * H_ + k0 + lc;
                const size_t gb = (size_t)(colBase + lr + i * 32) * H_ + k0 + lc;
                const uint32_t so = (uint32_t)(slot * SLOTS + (lr + i * 32) * STRS + lc) * 2;
                cp16(pAh + so, ah + ga);
                cp16(pAl + so, al + ga);
                cp16(pBh + so, g_WT_hi + gb);
                cp16(pBl + so, g_WT_lo + gb);
            }
            CP_COMMIT();
        };

        if (t > 0) bar_wait(grp, base + (unsigned)t);
        issueA(0, 0); issueA(1, 1); issueA(2, 2);

        float d[2][4][4] = {};   // [m-tile][n-tile][frag]

        #pragma unroll 1
        for (int kc = 0; kc < NK; kc++) {
            CP_WAIT(2);
            __syncthreads();
            if (kc + 3 < NK) issueWA((kc + 3) & 3, kc + 3);
            else             issueW((kc + 3 - NK) & 3, kc + 3 - NK);
            const uint32_t so = (uint32_t)((kc & 3) * SLOTS) * 2;
            compute_stage_k32(pAh + so, pAl + so, pBh + so, pBl + so,
                              a_off0, a_off1, b_off0, b_off1, khb, d);
        }

        // ---- split-K reduction: warps 4-7 -> smem -> warps 0-3 add ----
        __syncthreads();   // slot-3 reads (kc=31) done before overwrite
        if (tid >= 128) {
            const uint32_t bb = (tid < 192 ? redA : redB) + (uint32_t)(tid & 63) * 4;
            const float* dv = (const float*)d;
            #pragma unroll
            for (int r = 0; r < 32; r++)
                asm volatile("st.shared.f32 [%0], %1;" :: "r"(bb + (uint32_t)r * 264), "f"(dv[r]));
        }
        __syncthreads();

        if (tid < 128) {
            const uint32_t bb = (tid < 64 ? redA : redB) + (uint32_t)(tid & 63) * 4;
            float* dv = (float*)d;
            #pragma unroll
            for (int r = 0; r < 32; r++) {
                float v;
                asm volatile("ld.shared.f32 %0, [%1];" : "=f"(v) : "r"(bb + (uint32_t)r * 264));
                dv[r] += v;
            }

            // ---- epilogue (warps 0-3 only): h = tanh(xin + acc) ----
            const int g = lane >> 2, tg = lane & 3;
            #pragma unroll
            for (int mi = 0; mi < 2; mi++) {
                const int r0 = rowBase + mrow + mi * 16 + g;
                const int r1 = r0 + 8;
                #pragma unroll
                for (int nj = 0; nj < 4; nj++) {
                    const int col = colBase + ncol + nj * 8 + 2 * tg;
                    const size_t o0 = ((size_t)t * B_ + r0) * H_ + col;
                    const size_t o1 = ((size_t)t * B_ + r1) * H_ + col;
                    float2 x0 = *(const float2*)&g_xin[o0];
                    float2 x1 = *(const float2*)&g_xin[o1];
                    float h00 = tanhf(x0.x + d[mi][nj][0]);
                    float h01 = tanhf(x0.y + d[mi][nj][1]);
                    float h10 = tanhf(x1.x + d[mi][nj][2]);
                    float h11 = tanhf(x1.y + d[mi][nj][3]);
                    __nv_bfloat16 e0, f0, e1, f1, e2, f2, e3, f3;
                    split2(h00, e0, f0); split2(h01, e1, f1);
                    split2(h10, e2, f2); split2(h11, e3, f3);
                    const size_t w0 = (size_t)r0 * H_ + col;
                    const size_t w1 = (size_t)r1 * H_ + col;
                    *(__nv_bfloat162*)&whi[w0] = __halves2bfloat162(e0, e1);
                    *(__nv_bfloat162*)&wlo[w0] = __halves2bfloat162(f0, f1);
                    *(__nv_bfloat162*)&whi[w1] = __halves2bfloat162(e2, e3);
                    *(__nv_bfloat162*)&wlo[w1] = __halves2bfloat162(f2, f3);
                }
            }
        }

        if (t < T_ - 1) bar_arrive(grp, base + (unsigned)t + 1u);
        else            __syncthreads();
    }
    CP_WAIT(0);
}

// ---------------------------------------------------------------------------
// Output head: h reconstructed from bf16 hi+lo history
// ---------------------------------------------------------------------------
__global__ void __launch_bounds__(256) out_kernel(
    const float* __restrict__ lin_w,
    const float* __restrict__ lin_b,
    float* __restrict__ out)
{
    const int bt = blockIdx.x;
    const int t = bt / B_;
    const int b = bt % B_;
    const int tid = threadIdx.x;

    const __nv_bfloat16* hhi = g_hh_hi + ((size_t)t * B_ + b) * H_;
    const __nv_bfloat16* hlo = g_hh_lo + ((size_t)t * B_ + b) * H_;

    float hreg[H_ / 256];
    #pragma unroll
    for (int i = 0; i < H_ / 256; i++)
        hreg[i] = __bfloat162float(hhi[i * 256 + tid]) + __bfloat162float(hlo[i * 256 + tid]);

    float acc[O_];
    #pragma unroll
    for (int o = 0; o < O_; o++) {
        float s = 0.f;
        #pragma unroll
        for (int i = 0; i < H_ / 256; i++)
            s += hreg[i] * lin_w[(size_t)o * H_ + i * 256 + tid];
        acc[o] = s;
    }

    #pragma unroll
    for (int off = 16; off > 0; off >>= 1)
        #pragma unroll
        for (int o = 0; o < O_; o++)
            acc[o] += __shfl_xor_sync(0xFFFFFFFFu, acc[o], off);

    __shared__ float wsum[8][O_];
    const int lane = tid & 31;
    const int w = tid >> 5;
    if (lane == 0)
        #pragma unroll
        for (int o = 0; o < O_; o++)
            wsum[w][o] = acc[o];
    __syncthreads();

    if (tid < O_) {
        float s = lin_b[tid];
        #pragma unroll
        for (int ww = 0; ww < 8; ww++)
            s += wsum[ww][tid];
        out[((size_t)b * T_ + t) * O_ + tid] = s;
    }
}

// ---------------------------------------------------------------------------
extern "C" void kernel_launch(void* const* d_in, const int* in_sizes, int n_in,
                              void* d_out, int out_size)
{
    const float* x     = (const float*)d_in[0];
    const float* h0    = (const float*)d_in[1];
    const float* Win   = (const float*)d_in[2];
    const float* W     = (const float*)d_in[3];
    const float* lin_w = (const float*)d_in[4];
    const float* lin_b = (const float*)d_in[5];
    float* out = (float*)d_out;

    __nv_bfloat16 *xhi, *xlo, *winT_hi, *winT_lo, *wT_hi, *wT_lo, *hA_hi, *hA_lo;
    cudaGetSymbolAddress((void**)&xhi, g_xhi);
    cudaGetSymbolAddress((void**)&xlo, g_xlo);
    cudaGetSymbolAddress((void**)&winT_hi, g_WinT_hi);
    cudaGetSymbolAddress((void**)&winT_lo, g_WinT_lo);
    cudaGetSymbolAddress((void**)&wT_hi, g_WT_hi);
    cudaGetSymbolAddress((void**)&wT_lo, g_WT_lo);
    cudaGetSymbolAddress((void**)&hA_hi, g_hA_hi);
    cudaGetSymbolAddress((void**)&hA_lo, g_hA_lo);

    static bool attr_done = false;
    if (!attr_done) {
        cudaFuncSetAttribute(xin_gemm_kernel,
                             cudaFuncAttributeMaxDynamicSharedMemorySize, SMEM_X);
        cudaFuncSetAttribute(step_persistent_kernel,
                             cudaFuncAttributeMaxDynamicSharedMemorySize, SMEM_S);
        attr_done = true;
    }

    // Prologue
    decomp_kernel<<<4096, 256>>>(x, xhi, xlo, (size_t)M1 * I_ / 4);
    decomp_kernel<<<512, 256>>>(h0, hA_hi, hA_lo, (size_t)B_ * H_ / 4);
    transpose_decomp_kernel<<<dim3(H_ / 32, I_ / 32), dim3(32, 8)>>>(Win, I_, H_, winT_hi, winT_lo);
    transpose_decomp_kernel<<<dim3(H_ / 32, H_ / 32), dim3(32, 8)>>>(W, H_, H_, wT_hi, wT_lo);

    // Input projection
    xin_gemm_kernel<<<dim3(H_ / BN, M1 / BM), 256, SMEM_X>>>();

    // Full recurrence
    step_persistent_kernel<<<NBLK_STEP, 256, SMEM_S>>>();

    // Output head
    out_kernel<<<T_ * B_, 256>>>(lin_w, lin_b, out);
}

// round 13
// speedup vs baseline: 1.2949x; 1.2122x over previous
#include <cuda_runtime.h>
#include <cuda_fp16.h>
#include <cstdint>
#include <cstddef>

// ---------------------------------------------------------------------------
// Problem constants
// ---------------------------------------------------------------------------
#define B_  256
#define T_  100
#define I_  1024
#define H_  2048
#define O_  10
#define M1  (B_ * T_)   // 25600

// Tile: 64x64 CTA, 8 warps; BK=64
#define BM 64
#define BN 64
#define BKS 64
#define STRS 72                        // 144B rows; conflict-free ldmatrix
#define SLOTS (BM * STRS)              // 4608 elems per array per stage
#define NSTG 4
#define ABYTES (NSTG * SLOTS * 2)      // 36864 B per operand array

// step kernel: 3 arrays (A single, Wh, Wl)
#define SMEM_S  (3 * ABYTES)           // 110592 B
#define NBLK_STEP 128
#define NROWG 4
#define GRP_CTAS 32

// xin kernel: 4 arrays (Ah, Al, Bh, Bl), 3 stages
#define NSTG_X 3
#define ABYTESX (NSTG_X * SLOTS * 2)   // 27648 B
#define SMEM_X  (4 * ABYTESX)          // 110592 B

// ---------------------------------------------------------------------------
// Device scratch (all fp16 operands)
// ---------------------------------------------------------------------------
__device__ float  g_xin [(size_t)T_ * B_ * H_];         // [t][b][h]
__device__ __half g_hh  [(size_t)T_ * B_ * H_];         // h history (single fp16)
__device__ __half g_xhi[(size_t)M1 * I_];
__device__ __half g_xlo[(size_t)M1 * I_];
__device__ __half g_WinT_hi[(size_t)H_ * I_];           // [h][i]
__device__ __half g_WinT_lo[(size_t)H_ * I_];
__device__ __half g_WT_hi[(size_t)H_ * H_];             // [n][k]
__device__ __half g_WT_lo[(size_t)H_ * H_];
__device__ __half g_hA[(size_t)B_ * H_];                // h0 (single fp16)
__device__ unsigned g_bar_count4[NROWG] = {0, 0, 0, 0};
__device__ unsigned g_bar_sense4[NROWG] = {0, 0, 0, 0};

// ---------------------------------------------------------------------------
// Helpers
// ---------------------------------------------------------------------------
__device__ __forceinline__ uint32_t s2u(const void* p) {
    uint32_t a;
    asm("{ .reg .u64 t; cvta.to.shared.u64 t, %1; cvt.u32.u64 %0, t; }" : "=r"(a) : "l"(p));
    return a;
}
__device__ __forceinline__ void cp16(uint32_t s, const void* g) {
    asm volatile("cp.async.cg.shared.global [%0], [%1], 16;" :: "r"(s), "l"(g));
}
#define CP_COMMIT()  asm volatile("cp.async.commit_group;")
#define CP_WAIT(N)   asm volatile("cp.async.wait_group %0;" :: "n"(N))

__device__ __forceinline__ void mma_f16(float* d, const uint32_t* a, uint32_t b0, uint32_t b1) {
    asm volatile(
        "mma.sync.aligned.m16n8k16.row.col.f32.f16.f16.f32 "
        "{%0,%1,%2,%3}, {%4,%5,%6,%7}, {%8,%9}, {%0,%1,%2,%3};"
        : "+f"(d[0]), "+f"(d[1]), "+f"(d[2]), "+f"(d[3])
        : "r"(a[0]), "r"(a[1]), "r"(a[2]), "r"(a[3]), "r"(b0), "r"(b1));
}
__device__ __forceinline__ void ldsm4(uint32_t* r, uint32_t addr) {
    asm volatile("ldmatrix.sync.aligned.m8n8.x4.shared.b16 {%0,%1,%2,%3}, [%4];"
        : "=r"(r[0]), "=r"(r[1]), "=r"(r[2]), "=r"(r[3]) : "r"(addr));
}
__device__ __forceinline__ void split2h(float v, __half& h, __half& l) {
    h = __float2half(v);
    l = __float2half(v - __half2float(h));
}

__device__ __forceinline__ uint32_t a_lane_off(int mrow, int lane) {
    return (uint32_t)(((mrow + (lane & 15)) * STRS + ((lane >> 4) & 1) * 8) * 2);
}
__device__ __forceinline__ uint32_t b_lane_off(int ncol, int jp, int lane) {
    return (uint32_t)(((ncol + jp * 16 + ((lane >> 4) & 1) * 8 + (lane & 7)) * STRS
                       + ((lane >> 3) & 1) * 8) * 2);
}

// xin compute: warp 16x32, fp16 3-pass (Ah·Bh + Ah·Bl + Al·Bh)
__device__ __forceinline__ void compute_stage_x(
    uint32_t sAh, uint32_t sAl, uint32_t sBh, uint32_t sBl,
    uint32_t a_off, uint32_t b_off0, uint32_t b_off1, float (*d)[4])
{
    #pragma unroll
    for (int kh = 0; kh < 4; kh++) {
        const uint32_t ko = kh * 32;
        uint32_t ah[4], al[4], bh[4], bl[4];
        ldsm4(ah, sAh + a_off + ko);
        ldsm4(al, sAl + a_off + ko);
        ldsm4(bh, sBh + b_off0 + ko);
        ldsm4(bl, sBl + b_off0 + ko);
        mma_f16(d[0], ah, bh[0], bh[1]);
        mma_f16(d[0], ah, bl[0], bl[1]);
        mma_f16(d[0], al, bh[0], bh[1]);
        mma_f16(d[1], ah, bh[2], bh[3]);
        mma_f16(d[1], ah, bl[2], bl[3]);
        mma_f16(d[1], al, bh[2], bh[3]);
        ldsm4(bh, sBh + b_off1 + ko);
        ldsm4(bl, sBl + b_off1 + ko);
        mma_f16(d[2], ah, bh[0], bh[1]);
        mma_f16(d[2], ah, bl[0], bl[1]);
        mma_f16(d[2], al, bh[0], bh[1]);
        mma_f16(d[3], ah, bh[2], bh[3]);
        mma_f16(d[3], ah, bl[2], bl[3]);
        mma_f16(d[3], al, bh[2], bh[3]);
    }
}

// step compute: warp 32x32 over HALF the chunk K, fp16 2-pass (A·Wh + A·Wl)
__device__ __forceinline__ void compute_stage_k32_2p(
    uint32_t sA, uint32_t sBh, uint32_t sBl,
    uint32_t a_off0, uint32_t a_off1, uint32_t b_off0, uint32_t b_off1,
    int khb, float (*d)[4][4])   // d[mi][nj][4]
{
    #pragma unroll
    for (int i = 0; i < 2; i++) {
        const uint32_t ko = (khb + i) * 32;
        uint32_t a0[4], a1[4], bh0[4], bh1[4], bl0[4], bl1[4];
        ldsm4(a0, sA + a_off0 + ko);
        ldsm4(a1, sA + a_off1 + ko);
        ldsm4(bh0, sBh + b_off0 + ko);
        ldsm4(bh1, sBh + b_off1 + ko);
        ldsm4(bl0, sBl + b_off0 + ko);
        ldsm4(bl1, sBl + b_off1 + ko);
        mma_f16(d[0][0], a0, bh0[0], bh0[1]);
        mma_f16(d[0][1], a0, bh0[2], bh0[3]);
        mma_f16(d[0][2], a0, bh1[0], bh1[1]);
        mma_f16(d[0][3], a0, bh1[2], bh1[3]);
        mma_f16(d[0][0], a0, bl0[0], bl0[1]);
        mma_f16(d[0][1], a0, bl0[2], bl0[3]);
        mma_f16(d[0][2], a0, bl1[0], bl1[1]);
        mma_f16(d[0][3], a0, bl1[2], bl1[3]);
        mma_f16(d[1][0], a1, bh0[0], bh0[1]);
        mma_f16(d[1][1], a1, bh0[2], bh0[3]);
        mma_f16(d[1][2], a1, bh1[0], bh1[1]);
        mma_f16(d[1][3], a1, bh1[2], bh1[3]);
        mma_f16(d[1][0], a1, bl0[0], bl0[1]);
        mma_f16(d[1][1], a1, bl0[2], bl0[3]);
        mma_f16(d[1][2], a1, bl1[0], bl1[1]);
        mma_f16(d[1][3], a1, bl1[2], bl1[3]);
    }
}

// ---------------------------------------------------------------------------
// Prologue kernels
// ---------------------------------------------------------------------------
__global__ void decomp_split_kernel(const float* __restrict__ src,
                                    __half* __restrict__ hi,
                                    __half* __restrict__ lo, size_t n4) {
    for (size_t i = (size_t)blockIdx.x * blockDim.x + threadIdx.x; i < n4;
         i += (size_t)gridDim.x * blockDim.x) {
        float4 v = ((const float4*)src)[i];
        __half h0, l0, h1, l1, h2, l2, h3, l3;
        split2h(v.x, h0, l0); split2h(v.y, h1, l1);
        split2h(v.z, h2, l2); split2h(v.w, h3, l3);
        ((__half2*)hi)[i * 2 + 0] = __halves2half2(h0, h1);
        ((__half2*)hi)[i * 2 + 1] = __halves2half2(h2, h3);
        ((__half2*)lo)[i * 2 + 0] = __halves2half2(l0, l1);
        ((__half2*)lo)[i * 2 + 1] = __halves2half2(l2, l3);
    }
}

__global__ void decomp_single_kernel(const float* __restrict__ src,
                                     __half* __restrict__ dst, size_t n4) {
    for (size_t i = (size_t)blockIdx.x * blockDim.x + threadIdx.x; i < n4;
         i += (size_t)gridDim.x * blockDim.x) {
        float4 v = ((const float4*)src)[i];
        ((__half2*)dst)[i * 2 + 0] = __halves2half2(__float2half(v.x), __float2half(v.y));
        ((__half2*)dst)[i * 2 + 1] = __halves2half2(__float2half(v.z), __float2half(v.w));
    }
}

__global__ void transpose_decomp_kernel(const float* __restrict__ src, int R, int C,
                                        __half* __restrict__ dhi,
                                        __half* __restrict__ dlo) {
    __shared__ float tile[32][33];
    const int bx = blockIdx.x * 32;
    const int by = blockIdx.y * 32;
    const int tx = threadIdx.x, ty = threadIdx.y;
    #pragma unroll
    for (int j = 0; j < 32; j += 8)
        tile[ty + j][tx] = src[(size_t)(by + ty + j) * C + bx + tx];
    __syncthreads();
    #pragma unroll
    for (int j = 0; j < 32; j += 8) {
        float v = tile[tx][ty + j];
        size_t o = (size_t)(bx + ty + j) * R + by + tx;
        __half h, l; split2h(v, h, l);
        dhi[o] = h; dlo[o] = l;
    }
}

// ---------------------------------------------------------------------------
// xin GEMM: g_xin[t][b][:] = x @ Win.  fp16 3-pass, BK=64, 3-stage, 2 CTAs/SM.
// ---------------------------------------------------------------------------
__global__ void __launch_bounds__(256, 2) xin_gemm_kernel() {
    extern __shared__ __half sm[];
    const uint32_t sbase = s2u(sm);
    const uint32_t pAh = sbase;
    const uint32_t pAl = sbase + 1 * ABYTESX;
    const uint32_t pBh = sbase + 2 * ABYTESX;
    const uint32_t pBl = sbase + 3 * ABYTESX;

    const int tid = threadIdx.x;
    const int wid = tid >> 5, lane = tid & 31;
    const int mrow = (wid & 3) * 16;
    const int ncol = (wid >> 2) * 32;
    const int rowBase = blockIdx.y * BM;
    const int colBase = blockIdx.x * BN;
    const int lr = tid >> 3;
    const int lc = (tid & 7) * 8;
    constexpr int NK = I_ / BKS;   // 16

    const uint32_t a_off  = a_lane_off(mrow, lane);
    const uint32_t b_off0 = b_lane_off(ncol, 0, lane);
    const uint32_t b_off1 = b_lane_off(ncol, 1, lane);

    auto issue = [&](int slot, int kc) {
        const int k0 = kc * BKS;
        #pragma unroll
        for (int i = 0; i < 2; i++) {
            const size_t ga = (size_t)(rowBase + lr + i * 32) * I_ + k0 + lc;
            const size_t gb = (size_t)(colBase + lr + i * 32) * I_ + k0 + lc;
            const uint32_t so = (uint32_t)(slot * SLOTS + (lr + i * 32) * STRS + lc) * 2;
            cp16(pAh + so, g_xhi + ga);
            cp16(pAl + so, g_xlo + ga);
            cp16(pBh + so, g_WinT_hi + gb);
            cp16(pBl + so, g_WinT_lo + gb);
        }
        CP_COMMIT();
    };

    issue(0, 0); issue(1, 1);
    float d[4][4] = {};

    int slot = 0;
    #pragma unroll 1
    for (int kc = 0; kc < NK; kc++) {
        CP_WAIT(1);
        __syncthreads();
        if (kc + 2 < NK) {
            int s2 = slot + 2; if (s2 >= NSTG_X) s2 -= NSTG_X;
            issue(s2, kc + 2);
        }
        const uint32_t so = (uint32_t)(slot * SLOTS) * 2;
        compute_stage_x(pAh + so, pAl + so, pBh + so, pBl + so,
                        a_off, b_off0, b_off1, d);
        if (++slot == NSTG_X) slot = 0;
    }
    CP_WAIT(0);

    const int g = lane >> 2, tg = lane & 3;
    const int r0 = rowBase + mrow + g;
    const int r1 = r0 + 8;
    const int bb0 = r0 / T_, tt0 = r0 - bb0 * T_;
    const int bb1 = r1 / T_, tt1 = r1 - bb1 * T_;
    #pragma unroll
    for (int j = 0; j < 4; j++) {
        const int col = colBase + ncol + j * 8 + 2 * tg;
        *(float2*)&g_xin[((size_t)tt0 * B_ + bb0) * H_ + col] = make_float2(d[j][0], d[j][1]);
        *(float2*)&g_xin[((size_t)tt1 * B_ + bb1) * H_ + col] = make_float2(d[j][2], d[j][3]);
    }
}

// ---------------------------------------------------------------------------
// Per-rowgroup split grid barrier
// ---------------------------------------------------------------------------
__device__ __forceinline__ void bar_arrive(int grp, unsigned target) {
    __threadfence();
    __syncthreads();
    if (threadIdx.x == 0) {
        unsigned a = atomicAdd(&g_bar_count4[grp], 1);
        if (a == GRP_CTAS - 1) {
            atomicExch(&g_bar_count4[grp], 0);
            __threadfence();
            atomicExch(&g_bar_sense4[grp], target);
        }
    }
}
__device__ __forceinline__ void bar_wait(int grp, unsigned target) {
    if (threadIdx.x == 0) {
        while (atomicAdd(&g_bar_sense4[grp], 0) < target) { __nanosleep(64); }
    }
    __syncthreads();
}

// ---------------------------------------------------------------------------
// Persistent recurrence: fp16 2-pass, split-K, BK=64, 4 stages,
// cross-step W prefetch, rowgroup barriers.  h stored single fp16.
// ---------------------------------------------------------------------------
__global__ void __launch_bounds__(256) step_persistent_kernel() {
    extern __shared__ __half sm[];
    const uint32_t sbase = s2u(sm);
    const uint32_t pA  = sbase;
    const uint32_t pBh = sbase + 1 * ABYTES;
    const uint32_t pBl = sbase + 2 * ABYTES;

    const int tid = threadIdx.x;
    const int wid = tid >> 5, lane = tid & 31;
    const int mrow = (wid & 1) * 32;
    const int ncol = ((wid >> 1) & 1) * 32;
    const int khb  = (wid >> 2) * 2;
    const int bid = blockIdx.x;
    const int grp = bid >> 5;
    const int rowBase = grp * BM;
    const int colBase = (bid & 31) * BN;
    const int lr = tid >> 3;
    const int lc = (tid & 7) * 8;
    constexpr int NK = H_ / BKS;   // 32

    const uint32_t a_off0 = a_lane_off(mrow, lane);
    const uint32_t a_off1 = a_lane_off(mrow + 16, lane);
    const uint32_t b_off0 = b_lane_off(ncol, 0, lane);
    const uint32_t b_off1 = b_lane_off(ncol, 1, lane);

    // reduction exchange regions: slot 3 of pA / pBh (dead at step end;
    // tail W' prefetch writes only slots 0-2)
    const uint32_t redA = pA  + (uint32_t)(3 * SLOTS) * 2;
    const uint32_t redB = pBh + (uint32_t)(3 * SLOTS) * 2;

    __shared__ unsigned s_base;
    if (tid == 0) s_base = atomicAdd(&g_bar_sense4[grp], 0u);
    __syncthreads();
    const unsigned base = s_base;

    auto issueW = [&](int slot, int kc) {
        const int k0 = kc * BKS;
        #pragma unroll
        for (int i = 0; i < 2; i++) {
            const size_t gb = (size_t)(colBase + lr + i * 32) * H_ + k0 + lc;
            const uint32_t so = (uint32_t)(slot * SLOTS + (lr + i * 32) * STRS + lc) * 2;
            cp16(pBh + so, g_WT_hi + gb);
            cp16(pBl + so, g_WT_lo + gb);
        }
        CP_COMMIT();
    };

    issueW(0, 0); issueW(1, 1); issueW(2, 2);

    #pragma unroll 1
    for (int t = 0; t < T_; t++) {
        const __half* ah = (t == 0) ? g_hA : (g_hh + (size_t)(t - 1) * B_ * H_);

        auto issueA = [&](int slot, int kc) {
            const int k0 = kc * BKS;
            #pragma unroll
            for (int i = 0; i < 2; i++) {
                const size_t ga = (size_t)(rowBase + lr + i * 32) * H_ + k0 + lc;
                const uint32_t so = (uint32_t)(slot * SLOTS + (lr + i * 32) * STRS + lc) * 2;
                cp16(pA + so, ah + ga);
            }
            CP_COMMIT();
        };
        auto issueWA = [&](int slot, int kc) {
            const int k0 = kc * BKS;
            #pragma unroll
            for (int i = 0; i < 2; i++) {
                const size_t ga = (size_t)(rowBase + lr + i * 32) * H_ + k0 + lc;
                const size_t gb = (size_t)(colBase + lr + i * 32) * H_ + k0 + lc;
                const uint32_t so = (uint32_t)(slot * SLOTS + (lr + i * 32) * STRS + lc) * 2;
                cp16(pA + so, ah + ga);
                cp16(pBh + so, g_WT_hi + gb);
                cp16(pBl + so, g_WT_lo + gb);
            }
            CP_COMMIT();
        };

        if (t > 0) bar_wait(grp, base + (unsigned)t);
        issueA(0, 0); issueA(1, 1); issueA(2, 2);

        float d[2][4][4] = {};

        #pragma unroll 1
        for (int kc = 0; kc < NK; kc++) {
            CP_WAIT(2);
            __syncthreads();
            if (kc + 3 < NK) issueWA((kc + 3) & 3, kc + 3);
            else             issueW((kc + 3 - NK) & 3, kc + 3 - NK);
            const uint32_t so = (uint32_t)((kc & 3) * SLOTS) * 2;
            compute_stage_k32_2p(pA + so, pBh + so, pBl + so,
                                 a_off0, a_off1, b_off0, b_off1, khb, d);
        }

        // ---- split-K reduction: warps 4-7 -> smem -> warps 0-3 add ----
        __syncthreads();
        if (tid >= 128) {
            const uint32_t bb = (tid < 192 ? redA : redB) + (uint32_t)(tid & 63) * 4;
            const float* dv = (const float*)d;
            #pragma unroll
            for (int r = 0; r < 32; r++)
                asm volatile("st.shared.f32 [%0], %1;" :: "r"(bb + (uint32_t)r * 264), "f"(dv[r]));
        }
        __syncthreads();

        if (tid < 128) {
            const uint32_t bb = (tid < 64 ? redA : redB) + (uint32_t)(tid & 63) * 4;
            float* dv = (float*)d;
            #pragma unroll
            for (int r = 0; r < 32; r++) {
                float v;
                asm volatile("ld.shared.f32 %0, [%1];" : "=f"(v) : "r"(bb + (uint32_t)r * 264));
                dv[r] += v;
            }

            // ---- epilogue (warps 0-3): h = tanh(xin + acc) -> fp16 ----
            // NOTE: o0/o1 are ABSOLUTE offsets into g_hh (they already include
            // the t*B_ term) — R12's bug was adding t*B*H a second time.
            const int g = lane >> 2, tg = lane & 3;
            #pragma unroll
            for (int mi = 0; mi < 2; mi++) {
                const int r0 = rowBase + mrow + mi * 16 + g;
                const int r1 = r0 + 8;
                #pragma unroll
                for (int nj = 0; nj < 4; nj++) {
                    const int col = colBase + ncol + nj * 8 + 2 * tg;
                    const size_t o0 = ((size_t)t * B_ + r0) * H_ + col;
                    const size_t o1 = ((size_t)t * B_ + r1) * H_ + col;
                    float2 x0 = *(const float2*)&g_xin[o0];
                    float2 x1 = *(const float2*)&g_xin[o1];
                    float h00 = tanhf(x0.x + d[mi][nj][0]);
                    float h01 = tanhf(x0.y + d[mi][nj][1]);
                    float h10 = tanhf(x1.x + d[mi][nj][2]);
                    float h11 = tanhf(x1.y + d[mi][nj][3]);
                    *(__half2*)&g_hh[o0] = __halves2half2(__float2half(h00), __float2half(h01));
                    *(__half2*)&g_hh[o1] = __halves2half2(__float2half(h10), __float2half(h11));
                }
            }
        }

        if (t < T_ - 1) bar_arrive(grp, base + (unsigned)t + 1u);
        else            __syncthreads();
    }
    CP_WAIT(0);
}

// ---------------------------------------------------------------------------
// Output head: h read as single fp16
// ---------------------------------------------------------------------------
__global__ void __launch_bounds__(256) out_kernel(
    const float* __restrict__ lin_w,
    const float* __restrict__ lin_b,
    float* __restrict__ out)
{
    const int bt = blockIdx.x;
    const int t = bt / B_;
    const int b = bt % B_;
    const int tid = threadIdx.x;

    const __half* hrow = g_hh + ((size_t)t * B_ + b) * H_;

    float hreg[H_ / 256];
    #pragma unroll
    for (int i = 0; i < H_ / 256; i++)
        hreg[i] = __half2float(hrow[i * 256 + tid]);

    float acc[O_];
    #pragma unroll
    for (int o = 0; o < O_; o++) {
        float s = 0.f;
        #pragma unroll
        for (int i = 0; i < H_ / 256; i++)
            s += hreg[i] * lin_w[(size_t)o * H_ + i * 256 + tid];
        acc[o] = s;
    }

    #pragma unroll
    for (int off = 16; off > 0; off >>= 1)
        #pragma unroll
        for (int o = 0; o < O_; o++)
            acc[o] += __shfl_xor_sync(0xFFFFFFFFu, acc[o], off);

    __shared__ float wsum[8][O_];
    const int lane = tid & 31;
    const int w = tid >> 5;
    if (lane == 0)
        #pragma unroll
        for (int o = 0; o < O_; o++)
            wsum[w][o] = acc[o];
    __syncthreads();

    if (tid < O_) {
        float s = lin_b[tid];
        #pragma unroll
        for (int ww = 0; ww < 8; ww++)
            s += wsum[ww][tid];
        out[((size_t)b * T_ + t) * O_ + tid] = s;
    }
}

// ---------------------------------------------------------------------------
extern "C" void kernel_launch(void* const* d_in, const int* in_sizes, int n_in,
                              void* d_out, int out_size)
{
    const float* x     = (const float*)d_in[0];
    const float* h0    = (const float*)d_in[1];
    const float* Win   = (const float*)d_in[2];
    const float* W     = (const float*)d_in[3];
    const float* lin_w = (const float*)d_in[4];
    const float* lin_b = (const float*)d_in[5];
    float* out = (float*)d_out;

    __half *xhi, *xlo, *winT_hi, *winT_lo, *wT_hi, *wT_lo, *hA;
    cudaGetSymbolAddress((void**)&xhi, g_xhi);
    cudaGetSymbolAddress((void**)&xlo, g_xlo);
    cudaGetSymbolAddress((void**)&winT_hi, g_WinT_hi);
    cudaGetSymbolAddress((void**)&winT_lo, g_WinT_lo);
    cudaGetSymbolAddress((void**)&wT_hi, g_WT_hi);
    cudaGetSymbolAddress((void**)&wT_lo, g_WT_lo);
    cudaGetSymbolAddress((void**)&hA, g_hA);

    static bool attr_done = false;
    if (!attr_done) {
        cudaFuncSetAttribute(xin_gemm_kernel,
                             cudaFuncAttributeMaxDynamicSharedMemorySize, SMEM_X);
        cudaFuncSetAttribute(step_persistent_kernel,
                             cudaFuncAttributeMaxDynamicSharedMemorySize, SMEM_S);
        attr_done = true;
    }

    // Prologue
    decomp_split_kernel<<<4096, 256>>>(x, xhi, xlo, (size_t)M1 * I_ / 4);
    decomp_single_kernel<<<512, 256>>>(h0, hA, (size_t)B_ * H_ / 4);
    transpose_decomp_kernel<<<dim3(H_ / 32, I_ / 32), dim3(32, 8)>>>(Win, I_, H_, winT_hi, winT_lo);
    transpose_decomp_kernel<<<dim3(H_ / 32, H_ / 32), dim3(32, 8)>>>(W, H_, H_, wT_hi, wT_lo);

    // Input projection
    xin_gemm_kernel<<<dim3(H_ / BN, M1 / BM), 256, SMEM_X>>>();

    // Full recurrence
    step_persistent_kernel<<<NBLK_STEP, 256, SMEM_S>>>();

    // Output head
    out_kernel<<<T_ * B_, 256>>>(lin_w, lin_b, out);
}

// round 14
// speedup vs baseline: 1.3703x; 1.0582x over previous
#include <cuda_runtime.h>
#include <cuda_fp16.h>
#include <cstdint>
#include <cstddef>

// ---------------------------------------------------------------------------
// Problem constants
// ---------------------------------------------------------------------------
#define B_  256
#define T_  100
#define I_  1024
#define H_  2048
#define O_  10
#define M1  (B_ * T_)   // 25600

// Tile: 64x64 CTA, 8 warps; BK=64
#define BM 64
#define BN 64
#define BKS 64
#define STRS 72                        // 144B rows; conflict-free ldmatrix
#define SLOTS (BM * STRS)              // 4608 elems per array per stage
#define NSTG 4
#define ABYTES (NSTG * SLOTS * 2)      // 36864 B per operand array

// step kernel: 3 arrays (A single, Wh, Wl)
#define SMEM_S  (3 * ABYTES)           // 110592 B
#define NBLK_STEP 128
#define NROWG 4
#define GRP_CTAS 32

// xin kernel: 3 arrays (A single, Bh, Bl), 3 stages
#define NSTG_X 3
#define ABYTESX (NSTG_X * SLOTS * 2)   // 27648 B
#define SMEM_X  (3 * ABYTESX)          // 82944 B
// ---------------------------------------------------------------------------
// Device scratch (all fp16 operands)
// ---------------------------------------------------------------------------
__device__ float  g_xin [(size_t)T_ * B_ * H_];         // [t][b][h]
__device__ __half g_hh  [(size_t)T_ * B_ * H_];         // h history (single fp16)
__device__ __half g_x16 [(size_t)M1 * I_];              // x single fp16
__device__ __half g_WinT_hi[(size_t)H_ * I_];           // [h][i]
__device__ __half g_WinT_lo[(size_t)H_ * I_];
__device__ __half g_WT_hi[(size_t)H_ * H_];             // [n][k]
__device__ __half g_WT_lo[(size_t)H_ * H_];
__device__ __half g_hA[(size_t)B_ * H_];                // h0 (single fp16)
__device__ unsigned g_bar_count4[NROWG] = {0, 0, 0, 0};
__device__ unsigned g_bar_sense4[NROWG] = {0, 0, 0, 0};

// ---------------------------------------------------------------------------
// Helpers
// ---------------------------------------------------------------------------
__device__ __forceinline__ uint32_t s2u(const void* p) {
    uint32_t a;
    asm("{ .reg .u64 t; cvta.to.shared.u64 t, %1; cvt.u32.u64 %0, t; }" : "=r"(a) : "l"(p));
    return a;
}
__device__ __forceinline__ void cp16(uint32_t s, const void* g) {
    asm volatile("cp.async.cg.shared.global [%0], [%1], 16;" :: "r"(s), "l"(g));
}
#define CP_COMMIT()  asm volatile("cp.async.commit_group;")
#define CP_WAIT(N)   asm volatile("cp.async.wait_group %0;" :: "n"(N))

__device__ __forceinline__ void mma_f16(float* d, const uint32_t* a, uint32_t b0, uint32_t b1) {
    asm volatile(
        "mma.sync.aligned.m16n8k16.row.col.f32.f16.f16.f32 "
        "{%0,%1,%2,%3}, {%4,%5,%6,%7}, {%8,%9}, {%0,%1,%2,%3};"
        : "+f"(d[0]), "+f"(d[1]), "+f"(d[2]), "+f"(d[3])
        : "r"(a[0]), "r"(a[1]), "r"(a[2]), "r"(a[3]), "r"(b0), "r"(b1));
}
__device__ __forceinline__ void ldsm4(uint32_t* r, uint32_t addr) {
    asm volatile("ldmatrix.sync.aligned.m8n8.x4.shared.b16 {%0,%1,%2,%3}, [%4];"
        : "=r"(r[0]), "=r"(r[1]), "=r"(r[2]), "=r"(r[3]) : "r"(addr));
}
__device__ __forceinline__ void split2h(float v, __half& h, __half& l) {
    h = __float2half(v);
    l = __float2half(v - __half2float(h));
}

__device__ __forceinline__ uint32_t a_lane_off(int mrow, int lane) {
    return (uint32_t)(((mrow + (lane & 15)) * STRS + ((lane >> 4) & 1) * 8) * 2);
}
__device__ __forceinline__ uint32_t b_lane_off(int ncol, int jp, int lane) {
    return (uint32_t)(((ncol + jp * 16 + ((lane >> 4) & 1) * 8 + (lane & 7)) * STRS
                       + ((lane >> 3) & 1) * 8) * 2);
}

// xin compute: warp 16x32, fp16 2-pass (A·Bh + A·Bl).  5 ldsm4 + 8 MMA / k16.
__device__ __forceinline__ void compute_stage_x2p(
    uint32_t sA, uint32_t sBh, uint32_t sBl,
    uint32_t a_off, uint32_t b_off0, uint32_t b_off1, float (*d)[4])
{
    #pragma unroll
    for (int kh = 0; kh < 4; kh++) {
        const uint32_t ko = kh * 32;
        uint32_t a[4], bh[4], bl[4];
        ldsm4(a, sA + a_off + ko);
        ldsm4(bh, sBh + b_off0 + ko);
        ldsm4(bl, sBl + b_off0 + ko);
        mma_f16(d[0], a, bh[0], bh[1]);
        mma_f16(d[0], a, bl[0], bl[1]);
        mma_f16(d[1], a, bh[2], bh[3]);
        mma_f16(d[1], a, bl[2], bl[3]);
        ldsm4(bh, sBh + b_off1 + ko);
        ldsm4(bl, sBl + b_off1 + ko);
        mma_f16(d[2], a, bh[0], bh[1]);
        mma_f16(d[2], a, bl[0], bl[1]);
        mma_f16(d[3], a, bh[2], bh[3]);
        mma_f16(d[3], a, bl[2], bl[3]);
    }
}

// step compute: warp 32x32 over HALF the chunk K, fp16 2-pass (A·Wh + A·Wl)
__device__ __forceinline__ void compute_stage_k32_2p(
    uint32_t sA, uint32_t sBh, uint32_t sBl,
    uint32_t a_off0, uint32_t a_off1, uint32_t b_off0, uint32_t b_off1,
    int khb, float (*d)[4][4])   // d[mi][nj][4]
{
    #pragma unroll
    for (int i = 0; i < 2; i++) {
        const uint32_t ko = (khb + i) * 32;
        uint32_t a0[4], a1[4], bh0[4], bh1[4], bl0[4], bl1[4];
        ldsm4(a0, sA + a_off0 + ko);
        ldsm4(a1, sA + a_off1 + ko);
        ldsm4(bh0, sBh + b_off0 + ko);
        ldsm4(bh1, sBh + b_off1 + ko);
        ldsm4(bl0, sBl + b_off0 + ko);
        ldsm4(bl1, sBl + b_off1 + ko);
        mma_f16(d[0][0], a0, bh0[0], bh0[1]);
        mma_f16(d[0][1], a0, bh0[2], bh0[3]);
        mma_f16(d[0][2], a0, bh1[0], bh1[1]);
        mma_f16(d[0][3], a0, bh1[2], bh1[3]);
        mma_f16(d[0][0], a0, bl0[0], bl0[1]);
        mma_f16(d[0][1], a0, bl0[2], bl0[3]);
        mma_f16(d[0][2], a0, bl1[0], bl1[1]);
        mma_f16(d[0][3], a0, bl1[2], bl1[3]);
        mma_f16(d[1][0], a1, bh0[0], bh0[1]);
        mma_f16(d[1][1], a1, bh0[2], bh0[3]);
        mma_f16(d[1][2], a1, bh1[0], bh1[1]);
        mma_f16(d[1][3], a1, bh1[2], bh1[3]);
        mma_f16(d[1][0], a1, bl0[0], bl0[1]);
        mma_f16(d[1][1], a1, bl0[2], bl0[3]);
        mma_f16(d[1][2], a1, bl1[0], bl1[1]);
        mma_f16(d[1][3], a1, bl1[2], bl1[3]);
    }
}

// ---------------------------------------------------------------------------
// Prologue kernels
// ---------------------------------------------------------------------------
__global__ void decomp_single_kernel(const float* __restrict__ src,
                                     __half* __restrict__ dst, size_t n4) {
    for (size_t i = (size_t)blockIdx.x * blockDim.x + threadIdx.x; i < n4;
         i += (size_t)gridDim.x * blockDim.x) {
        float4 v = ((const float4*)src)[i];
        ((__half2*)dst)[i * 2 + 0] = __halves2half2(__float2half(v.x), __float2half(v.y));
        ((__half2*)dst)[i * 2 + 1] = __halves2half2(__float2half(v.z), __float2half(v.w));
    }
}

__global__ void transpose_decomp_kernel(const float* __restrict__ src, int R, int C,
                                        __half* __restrict__ dhi,
                                        __half* __restrict__ dlo) {
    __shared__ float tile[32][33];
    const int bx = blockIdx.x * 32;
    const int by = blockIdx.y * 32;
    const int tx = threadIdx.x, ty = threadIdx.y;
    #pragma unroll
    for (int j = 0; j < 32; j += 8)
        tile[ty + j][tx] = src[(size_t)(by + ty + j) * C + bx + tx];
    __syncthreads();
    #pragma unroll
    for (int j = 0; j < 32; j += 8) {
        float v = tile[tx][ty + j];
        size_t o = (size_t)(bx + ty + j) * R + by + tx;
        __half h, l; split2h(v, h, l);
        dhi[o] = h; dlo[o] = l;
    }
}

// ---------------------------------------------------------------------------
// xin GEMM: g_xin[t][b][:] = x @ Win.  fp16 2-pass, BK=64, 3-stage, 2 CTAs/SM.
// ---------------------------------------------------------------------------
__global__ void __launch_bounds__(256, 2) xin_gemm_kernel() {
    extern __shared__ __half sm[];
    const uint32_t sbase = s2u(sm);
    const uint32_t pA  = sbase;
    const uint32_t pBh = sbase + 1 * ABYTESX;
    const uint32_t pBl = sbase + 2 * ABYTESX;

    const int tid = threadIdx.x;
    const int wid = tid >> 5, lane = tid & 31;
    const int mrow = (wid & 3) * 16;
    const int ncol = (wid >> 2) * 32;
    const int rowBase = blockIdx.y * BM;
    const int colBase = blockIdx.x * BN;
    const int lr = tid >> 3;
    const int lc = (tid & 7) * 8;
    constexpr int NK = I_ / BKS;   // 16

    const uint32_t a_off  = a_lane_off(mrow, lane);
    const uint32_t b_off0 = b_lane_off(ncol, 0, lane);
    const uint32_t b_off1 = b_lane_off(ncol, 1, lane);

    auto issue = [&](int slot, int kc) {
        const int k0 = kc * BKS;
        #pragma unroll
        for (int i = 0; i < 2; i++) {
            const size_t ga = (size_t)(rowBase + lr + i * 32) * I_ + k0 + lc;
            const size_t gb = (size_t)(colBase + lr + i * 32) * I_ + k0 + lc;
            const uint32_t so = (uint32_t)(slot * SLOTS + (lr + i * 32) * STRS + lc) * 2;
            cp16(pA + so, g_x16 + ga);
            cp16(pBh + so, g_WinT_hi + gb);
            cp16(pBl + so, g_WinT_lo + gb);
        }
        CP_COMMIT();
    };

    issue(0, 0); issue(1, 1);
    float d[4][4] = {};

    int slot = 0;
    #pragma unroll 1
    for (int kc = 0; kc < NK; kc++) {
        CP_WAIT(1);
        __syncthreads();
        if (kc + 2 < NK) {
            int s2 = slot + 2; if (s2 >= NSTG_X) s2 -= NSTG_X;
            issue(s2, kc + 2);
        }
        const uint32_t so = (uint32_t)(slot * SLOTS) * 2;
        compute_stage_x2p(pA + so, pBh + so, pBl + so,
                          a_off, b_off0, b_off1, d);
        if (++slot == NSTG_X) slot = 0;
    }
    CP_WAIT(0);

    const int g = lane >> 2, tg = lane & 3;
    const int r0 = rowBase + mrow + g;
    const int r1 = r0 + 8;
    const int bb0 = r0 / T_, tt0 = r0 - bb0 * T_;
    const int bb1 = r1 / T_, tt1 = r1 - bb1 * T_;
    #pragma unroll
    for (int j = 0; j < 4; j++) {
        const int col = colBase + ncol + j * 8 + 2 * tg;
        *(float2*)&g_xin[((size_t)tt0 * B_ + bb0) * H_ + col] = make_float2(d[j][0], d[j][1]);
        *(float2*)&g_xin[((size_t)tt1 * B_ + bb1) * H_ + col] = make_float2(d[j][2], d[j][3]);
    }
}

// ---------------------------------------------------------------------------
// Per-rowgroup split grid barrier
// ---------------------------------------------------------------------------
__device__ __forceinline__ void bar_arrive(int grp, unsigned target) {
    __threadfence();
    __syncthreads();
    if (threadIdx.x == 0) {
        unsigned a = atomicAdd(&g_bar_count4[grp], 1);
        if (a == GRP_CTAS - 1) {
            atomicExch(&g_bar_count4[grp], 0);
            __threadfence();
            atomicExch(&g_bar_sense4[grp], target);
        }
    }
}
__device__ __forceinline__ void bar_wait(int grp, unsigned target) {
    if (threadIdx.x == 0) {
        while (atomicAdd(&g_bar_sense4[grp], 0) < target) { __nanosleep(64); }
    }
    __syncthreads();
}

// ---------------------------------------------------------------------------
// Persistent recurrence: fp16 2-pass, split-K, BK=64, 4 stages,
// cross-step W prefetch, rowgroup barriers.  h stored single fp16.  (R13)
// ---------------------------------------------------------------------------
__global__ void __launch_bounds__(256) step_persistent_kernel() {
    extern __shared__ __half sm[];
    const uint32_t sbase = s2u(sm);
    const uint32_t pA  = sbase;
    const uint32_t pBh = sbase + 1 * ABYTES;
    const uint32_t pBl = sbase + 2 * ABYTES;

    const int tid = threadIdx.x;
    const int wid = tid >> 5, lane = tid & 31;
    const int mrow = (wid & 1) * 32;
    const int ncol = ((wid >> 1) & 1) * 32;
    const int khb  = (wid >> 2) * 2;
    const int bid = blockIdx.x;
    const int grp = bid >> 5;
    const int rowBase = grp * BM;
    const int colBase = (bid & 31) * BN;
    const int lr = tid >> 3;
    const int lc = (tid & 7) * 8;
    constexpr int NK = H_ / BKS;   // 32

    const uint32_t a_off0 = a_lane_off(mrow, lane);
    const uint32_t a_off1 = a_lane_off(mrow + 16, lane);
    const uint32_t b_off0 = b_lane_off(ncol, 0, lane);
    const uint32_t b_off1 = b_lane_off(ncol, 1, lane);

    const uint32_t redA = pA  + (uint32_t)(3 * SLOTS) * 2;
    const uint32_t redB = pBh + (uint32_t)(3 * SLOTS) * 2;

    __shared__ unsigned s_base;
    if (tid == 0) s_base = atomicAdd(&g_bar_sense4[grp], 0u);
    __syncthreads();
    const unsigned base = s_base;

    auto issueW = [&](int slot, int kc) {
        const int k0 = kc * BKS;
        #pragma unroll
        for (int i = 0; i < 2; i++) {
            const size_t gb = (size_t)(colBase + lr + i * 32) * H_ + k0 + lc;
            const uint32_t so = (uint32_t)(slot * SLOTS + (lr + i * 32) * STRS + lc) * 2;
            cp16(pBh + so, g_WT_hi + gb);
            cp16(pBl + so, g_WT_lo + gb);
        }
        CP_COMMIT();
    };

    issueW(0, 0); issueW(1, 1); issueW(2, 2);

    #pragma unroll 1
    for (int t = 0; t < T_; t++) {
        const __half* ah = (t == 0) ? g_hA : (g_hh + (size_t)(t - 1) * B_ * H_);

        auto issueA = [&](int slot, int kc) {
            const int k0 = kc * BKS;
            #pragma unroll
            for (int i = 0; i < 2; i++) {
                const size_t ga = (size_t)(rowBase + lr + i * 32) * H_ + k0 + lc;
                const uint32_t so = (uint32_t)(slot * SLOTS + (lr + i * 32) * STRS + lc) * 2;
                cp16(pA + so, ah + ga);
            }
            CP_COMMIT();
        };
        auto issueWA = [&](int slot, int kc) {
            const int k0 = kc * BKS;
            #pragma unroll
            for (int i = 0; i < 2; i++) {
                const size_t ga = (size_t)(rowBase + lr + i * 32) * H_ + k0 + lc;
                const size_t gb = (size_t)(colBase + lr + i * 32) * H_ + k0 + lc;
                const uint32_t so = (uint32_t)(slot * SLOTS + (lr + i * 32) * STRS + lc) * 2;
                cp16(pA + so, ah + ga);
                cp16(pBh + so, g_WT_hi + gb);
                cp16(pBl + so, g_WT_lo + gb);
            }
            CP_COMMIT();
        };

        if (t > 0) bar_wait(grp, base + (unsigned)t);
        issueA(0, 0); issueA(1, 1); issueA(2, 2);

        float d[2][4][4] = {};

        #pragma unroll 1
        for (int kc = 0; kc < NK; kc++) {
            CP_WAIT(2);
            __syncthreads();
            if (kc + 3 < NK) issueWA((kc + 3) & 3, kc + 3);
            else             issueW((kc + 3 - NK) & 3, kc + 3 - NK);
            const uint32_t so = (uint32_t)((kc & 3) * SLOTS) * 2;
            compute_stage_k32_2p(pA + so, pBh + so, pBl + so,
                                 a_off0, a_off1, b_off0, b_off1, khb, d);
        }

        // ---- split-K reduction: warps 4-7 -> smem -> warps 0-3 add ----
        __syncthreads();
        if (tid >= 128) {
            const uint32_t bb = (tid < 192 ? redA : redB) + (uint32_t)(tid & 63) * 4;
            const float* dv = (const float*)d;
            #pragma unroll
            for (int r = 0; r < 32; r++)
                asm volatile("st.shared.f32 [%0], %1;" :: "r"(bb + (uint32_t)r * 264), "f"(dv[r]));
        }
        __syncthreads();

        if (tid < 128) {
            const uint32_t bb = (tid < 64 ? redA : redB) + (uint32_t)(tid & 63) * 4;
            float* dv = (float*)d;
            #pragma unroll
            for (int r = 0; r < 32; r++) {
                float v;
                asm volatile("ld.shared.f32 %0, [%1];" : "=f"(v) : "r"(bb + (uint32_t)r * 264));
                dv[r] += v;
            }

            // ---- epilogue (warps 0-3): h = tanh(xin + acc) -> fp16 ----
            // o0/o1 are ABSOLUTE g_hh offsets (include t*B_ term).
            const int g = lane >> 2, tg = lane & 3;
            #pragma unroll
            for (int mi = 0; mi < 2; mi++) {
                const int r0 = rowBase + mrow + mi * 16 + g;
                const int r1 = r0 + 8;
                #pragma unroll
                for (int nj = 0; nj < 4; nj++) {
                    const int col = colBase + ncol + nj * 8 + 2 * tg;
                    const size_t o0 = ((size_t)t * B_ + r0) * H_ + col;
                    const size_t o1 = ((size_t)t * B_ + r1) * H_ + col;
                    float2 x0 = *(const float2*)&g_xin[o0];
                    float2 x1 = *(const float2*)&g_xin[o1];
                    float h00 = tanhf(x0.x + d[mi][nj][0]);
                    float h01 = tanhf(x0.y + d[mi][nj][1]);
                    float h10 = tanhf(x1.x + d[mi][nj][2]);
                    float h11 = tanhf(x1.y + d[mi][nj][3]);
                    *(__half2*)&g_hh[o0] = __halves2half2(__float2half(h00), __float2half(h01));
                    *(__half2*)&g_hh[o1] = __halves2half2(__float2half(h10), __float2half(h11));
                }
            }
        }

        if (t < T_ - 1) bar_arrive(grp, base + (unsigned)t + 1u);
        else            __syncthreads();
    }
    CP_WAIT(0);
}

// ---------------------------------------------------------------------------
// Output head: h read as single fp16
// ---------------------------------------------------------------------------
__global__ void __launch_bounds__(256) out_kernel(
    const float* __restrict__ lin_w,
    const float* __restrict__ lin_b,
    float* __restrict__ out)
{
    const int bt = blockIdx.x;
    const int t = bt / B_;
    const int b = bt % B_;
    const int tid = threadIdx.x;

    const __half* hrow = g_hh + ((size_t)t * B_ + b) * H_;

    float hreg[H_ / 256];
    #pragma unroll
    for (int i = 0; i < H_ / 256; i++)
        hreg[i] = __half2float(hrow[i * 256 + tid]);

    float acc[O_];
    #pragma unroll
    for (int o = 0; o < O_; o++) {
        float s = 0.f;
        #pragma unroll
        for (int i = 0; i < H_ / 256; i++)
            s += hreg[i] * lin_w[(size_t)o * H_ + i * 256 + tid];
        acc[o] = s;
    }

    #pragma unroll
    for (int off = 16; off > 0; off >>= 1)
        #pragma unroll
        for (int o = 0; o < O_; o++)
            acc[o] += __shfl_xor_sync(0xFFFFFFFFu, acc[o], off);

    __shared__ float wsum[8][O_];
    const int lane = tid & 31;
    const int w = tid >> 5;
    if (lane == 0)
        #pragma unroll
        for (int o = 0; o < O_; o++)
            wsum[w][o] = acc[o];
    __syncthreads();

    if (tid < O_) {
        float s = lin_b[tid];
        #pragma unroll
        for (int ww = 0; ww < 8; ww++)
            s += wsum[ww][tid];
        out[((size_t)b * T_ + t) * O_ + tid] = s;
    }
}

// ---------------------------------------------------------------------------
extern "C" void kernel_launch(void* const* d_in, const int* in_sizes, int n_in,
                              void* d_out, int out_size)
{
    const float* x     = (const float*)d_in[0];
    const float* h0    = (const float*)d_in[1];
    const float* Win   = (const float*)d_in[2];
    const float* W     = (const float*)d_in[3];
    const float* lin_w = (const float*)d_in[4];
    const float* lin_b = (const float*)d_in[5];
    float* out = (float*)d_out;

    __half *x16, *winT_hi, *winT_lo, *wT_hi, *wT_lo, *hA;
    cudaGetSymbolAddress((void**)&x16, g_x16);
    cudaGetSymbolAddress((void**)&winT_hi, g_WinT_hi);
    cudaGetSymbolAddress((void**)&winT_lo, g_WinT_lo);
    cudaGetSymbolAddress((void**)&wT_hi, g_WT_hi);
    cudaGetSymbolAddress((void**)&wT_lo, g_WT_lo);
    cudaGetSymbolAddress((void**)&hA, g_hA);

    static bool attr_done = false;
    if (!attr_done) {
        cudaFuncSetAttribute(xin_gemm_kernel,
                             cudaFuncAttributeMaxDynamicSharedMemorySize, SMEM_X);
        cudaFuncSetAttribute(step_persistent_kernel,
                             cudaFuncAttributeMaxDynamicSharedMemorySize, SMEM_S);
        attr_done = true;
    }

    // Prologue
    decomp_single_kernel<<<4096, 256>>>(x, x16, (size_t)M1 * I_ / 4);
    decomp_single_kernel<<<512, 256>>>(h0, hA, (size_t)B_ * H_ / 4);
    transpose_decomp_kernel<<<dim3(H_ / 32, I_ / 32), dim3(32, 8)>>>(Win, I_, H_, winT_hi, winT_lo);
    transpose_decomp_kernel<<<dim3(H_ / 32, H_ / 32), dim3(32, 8)>>>(W, H_, H_, wT_hi, wT_lo);

    // Input projection
    xin_gemm_kernel<<<dim3(H_ / BN, M1 / BM), 256, SMEM_X>>>();

    // Full recurrence
    step_persistent_kernel<<<NBLK_STEP, 256, SMEM_S>>>();

    // Output head
    out_kernel<<<T_ * B_, 256>>>(lin_w, lin_b, out);
}